// round 9
// baseline (speedup 1.0000x reference)
#include <cuda_runtime.h>
#include <cstddef>
#include <cstdint>

#define HDIM 64
#define NMAX 100352

// ---------------- scratch (static device globals; no allocation allowed) ----
__device__ float g_aggu[(size_t)NMAX * HDIM];
__device__ float g_aggb[(size_t)NMAX * HDIM];
__device__ float g_y1u[(size_t)NMAX * HDIM];
__device__ float g_y1b[(size_t)NMAX * HDIM];
__device__ float g_y2[(size_t)NMAX * 2 * HDIM];
__device__ float g_stats[5 * 128];     // per BN: [0..63]=sum, [64..127]=sumsq

// ---------------- init: agg = (1+eps)*x, zero stats ------------------------
__global__ void init_kernel(const float* __restrict__ x,
                            const float* __restrict__ eps1,
                            const float* __restrict__ eps2,
                            float* __restrict__ aggu,
                            float* __restrict__ aggb,
                            float* __restrict__ stats,
                            int total4)
{
    int i = blockIdx.x * blockDim.x + threadIdx.x;
    if (i < 5 * 128) stats[i] = 0.0f;
    float a = 1.0f + __ldg(eps1);
    float b = 1.0f + __ldg(eps2);
    const float4* x4 = (const float4*)x;
    float4* u4 = (float4*)aggu;
    float4* b4 = (float4*)aggb;
    int stride = gridDim.x * blockDim.x;
    for (int t = i; t < total4; t += stride) {
        float4 v = x4[t];
        float4 r;
        r.x = a * v.x; r.y = a * v.y; r.z = a * v.z; r.w = a * v.w;
        u4[t] = r;
        float4 s;
        s.x = b * v.x; s.y = b * v.y; s.z = b * v.z; s.w = b * v.w;
        b4[t] = s;
    }
}

// ---------------- merged scatter-add for both edge sets ---------------------
// Work item = one 16-byte chunk of one edge. 16 chunks per edge (H=64).
__global__ void scatter2_kernel(const float* __restrict__ featu,
                                const int* __restrict__ du,
                                const int* __restrict__ su, int EU,
                                const float* __restrict__ featb,
                                const int* __restrict__ db,
                                const int* __restrict__ sb, int EB,
                                float* __restrict__ aggu,
                                float* __restrict__ aggb)
{
    long t = blockIdx.x * (long)blockDim.x + threadIdx.x;
    long stride = gridDim.x * (long)blockDim.x;
    long total = (long)(EU + EB) * 16;
    for (long i = t; i < total; i += stride) {
        int e = (int)(i >> 4);
        int c = (int)(i & 15);
        const float* feat;
        float* agg;
        int dst, src;
        if (e < EU) {
            dst = __ldg(&du[e]);
            src = __ldg(&su[e]);
            feat = featu; agg = aggu;
        } else {
            int eb = e - EU;
            dst = __ldg(&db[eb]);
            src = __ldg(&sb[eb]);
            feat = featb; agg = aggb;
        }
        float4 v = *(const float4*)(feat + ((size_t)src << 6) + c * 4);
        float* p = agg + ((size_t)dst << 6) + c * 4;
        asm volatile("red.global.add.v4.f32 [%0], {%1,%2,%3,%4};"
                     :: "l"(p), "f"(v.x), "f"(v.y), "f"(v.z), "f"(v.w)
                     : "memory");
    }
}

// ---------------- f32x2 helpers --------------------------------------------
__device__ __forceinline__ unsigned long long dup2(float v) {
    unsigned long long r;
    asm("mov.b64 %0, {%1, %1};" : "=l"(r) : "r"(__float_as_uint(v)));
    return r;
}
__device__ __forceinline__ void ffma2(unsigned long long& d,
                                      unsigned long long a,
                                      unsigned long long b) {
    asm("fma.rn.f32x2 %0, %1, %2, %0;" : "+l"(d) : "l"(a), "l"(b));
}
__device__ __forceinline__ float2 unpk(unsigned long long v) {
    unsigned int lo, hi;
    asm("mov.b64 {%0, %1}, %2;" : "=r"(lo), "=r"(hi) : "l"(v));
    return make_float2(__uint_as_float(lo), __uint_as_float(hi));
}

// ---------------- GEMM + bias + fused input BN(from stats)+ReLU + BN stats --
// Y[i][j] = sum_k act(A[i][k]) * W[k][j] + bias[j]
// AFF: in-kernel coeffs from inStats/inG/inBe (two 64-col sets for K=128).
// Tile: 256 rows x 64 cols, 256 threads, 8x8 microtile, f32x2 packed math.
struct GArg {
    const float* A;
    const float* W;
    const float* bias;
    const float* st0; const float* g0; const float* be0;
    const float* st1; const float* g1; const float* be1;
    float* Y;
    float* stats;
};

template <int K, bool AFF>
__global__ __launch_bounds__(256, 2)
void gemm_bn(GArg ga, GArg gb, int ldY, int N, float invN)
{
    __shared__ float As[32][260];   // transposed A chunk: As[k][row]
    __shared__ float Ws[32][64];    // W chunk: Ws[k][col]
    __shared__ float sSc[AFF ? K : 1];
    __shared__ float sSh[AFF ? K : 1];

    const GArg g = (blockIdx.y == 0) ? ga : gb;

    const int tid  = threadIdx.x;         // 0..255
    const int lane = tid & 31;
    const int wy   = tid >> 5;            // col group (8 cols), 0..7
    const int rbase = blockIdx.x * 256;

    if (AFF) {
        if (tid < K) {
            const float* st = (tid < 64) ? g.st0 : g.st1;
            const float* gg = (tid < 64) ? g.g0  : g.g1;
            const float* bb = (tid < 64) ? g.be0 : g.be1;
            int j = tid & 63;
            float mean = st[j] * invN;
            float var  = st[64 + j] * invN - mean * mean;
            float s = gg[j] * rsqrtf(var + 1e-5f);
            sSc[tid] = s;
            sSh[tid] = bb[j] - mean * s;
        }
        __syncthreads();
    }

    unsigned long long acc[8][4];
#pragma unroll
    for (int i = 0; i < 8; i++)
#pragma unroll
        for (int p = 0; p < 4; p++) acc[i][p] = 0ull;

#pragma unroll
    for (int kc = 0; kc < K; kc += 32) {
        // --- load A chunk (256 rows x 32 cols), transform, transpose-store
#pragma unroll
        for (int it = 0; it < 8; it++) {
            int lin = it * 256 + tid;     // 2048 float4 slots
            int r   = lin >> 3;           // 8 float4 per row
            int c4  = lin & 7;
            int gr  = rbase + r;
            float4 v = make_float4(0.f, 0.f, 0.f, 0.f);
            if (gr < N)
                v = *(const float4*)&g.A[(size_t)gr * K + kc + c4 * 4];
            if (AFF) {
                int c = kc + c4 * 4;
                float4 s = *(const float4*)&sSc[c];
                float4 h = *(const float4*)&sSh[c];
                v.x = fmaxf(v.x * s.x + h.x, 0.f);
                v.y = fmaxf(v.y * s.y + h.y, 0.f);
                v.z = fmaxf(v.z * s.z + h.z, 0.f);
                v.w = fmaxf(v.w * s.w + h.w, 0.f);
            }
            As[c4 * 4 + 0][r] = v.x;
            As[c4 * 4 + 1][r] = v.y;
            As[c4 * 4 + 2][r] = v.z;
            As[c4 * 4 + 3][r] = v.w;
        }
        // --- load W chunk (32 rows x 64 cols)
#pragma unroll
        for (int it = 0; it < 2; it++) {
            int lin = it * 256 + tid;     // 512 float4
            int r   = lin >> 4;
            int c4  = lin & 15;
            *(float4*)&Ws[r][c4 * 4] = *(const float4*)&g.W[(size_t)(kc + r) * 64 + c4 * 4];
        }
        __syncthreads();

        // --- compute (f32x2 packed cols, 8 rows per thread)
#pragma unroll
        for (int k = 0; k < 32; k++) {
            float4 alo = *(const float4*)&As[k][lane * 4];
            float4 ahi = *(const float4*)&As[k][128 + lane * 4];
            ulonglong2 w03 = *(const ulonglong2*)&Ws[k][wy * 8];
            ulonglong2 w47 = *(const ulonglong2*)&Ws[k][wy * 8 + 4];
            unsigned long long wp[4] = { w03.x, w03.y, w47.x, w47.y };
            unsigned long long ad[8] = {
                dup2(alo.x), dup2(alo.y), dup2(alo.z), dup2(alo.w),
                dup2(ahi.x), dup2(ahi.y), dup2(ahi.z), dup2(ahi.w)
            };
#pragma unroll
            for (int i = 0; i < 8; i++)
#pragma unroll
                for (int p = 0; p < 4; p++)
                    ffma2(acc[i][p], ad[i], wp[p]);
        }
        if (kc + 32 < K) __syncthreads();
    }

    // --- epilogue: bias, store, per-warp stats reduction
    float b[8];
    *(float4*)&b[0] = *(const float4*)&g.bias[wy * 8];
    *(float4*)&b[4] = *(const float4*)&g.bias[wy * 8 + 4];

    float psum[8], psq[8];
#pragma unroll
    for (int j = 0; j < 8; j++) { psum[j] = 0.f; psq[j] = 0.f; }

#pragma unroll
    for (int i = 0; i < 8; i++) {
        int gr = rbase + ((i < 4) ? (lane * 4 + i) : (128 + lane * 4 + i - 4));
        if (gr < N) {
            float v[8];
#pragma unroll
            for (int p = 0; p < 4; p++) {
                float2 t = unpk(acc[i][p]);
                v[2 * p + 0] = t.x + b[2 * p + 0];
                v[2 * p + 1] = t.y + b[2 * p + 1];
            }
#pragma unroll
            for (int j = 0; j < 8; j++) {
                psum[j] += v[j];
                psq[j]  += v[j] * v[j];
            }
            float* yp = &g.Y[(size_t)gr * ldY + wy * 8];
            *(float4*)&yp[0] = *(float4*)&v[0];
            *(float4*)&yp[4] = *(float4*)&v[4];
        }
    }
    // warp-wide reduce (all lanes participate; OOB rows contributed 0)
#pragma unroll
    for (int j = 0; j < 8; j++) {
#pragma unroll
        for (int o = 16; o > 0; o >>= 1) {
            psum[j] += __shfl_xor_sync(0xFFFFFFFFu, psum[j], o);
            psq[j]  += __shfl_xor_sync(0xFFFFFFFFu, psq[j],  o);
        }
    }
    if (lane == 0) {
#pragma unroll
        for (int j = 0; j < 8; j++) {
            atomicAdd(&g.stats[wy * 8 + j], psum[j]);
            atomicAdd(&g.stats[64 + wy * 8 + j], psq[j]);
        }
    }
}

// ---------------- final BN + ReLU (coeffs in-kernel) ------------------------
__global__ void bnrelu_kernel(float* __restrict__ Y,
                              const float* __restrict__ stats,
                              const float* __restrict__ g,
                              const float* __restrict__ be,
                              int total4, float invN)
{
    __shared__ float sc[64], sh[64];
    if (threadIdx.x < 64) {
        int j = threadIdx.x;
        float mean = stats[j] * invN;
        float var  = stats[64 + j] * invN - mean * mean;
        float s = g[j] * rsqrtf(var + 1e-5f);
        sc[j] = s;
        sh[j] = be[j] - mean * s;
    }
    __syncthreads();
    int i = blockIdx.x * blockDim.x + threadIdx.x;
    int stride = gridDim.x * blockDim.x;
    float4* y4 = (float4*)Y;
    for (int t = i; t < total4; t += stride) {
        int c = (t * 4) & 63;
        float4 v = y4[t];
        float4 s = *(const float4*)&sc[c];
        float4 h = *(const float4*)&sh[c];
        v.x = fmaxf(v.x * s.x + h.x, 0.f);
        v.y = fmaxf(v.y * s.y + h.y, 0.f);
        v.z = fmaxf(v.z * s.z + h.z, 0.f);
        v.w = fmaxf(v.w * s.w + h.w, 0.f);
        y4[t] = v;
    }
}

// ---------------- launch ----------------------------------------------------
extern "C" void kernel_launch(void* const* d_in, const int* in_sizes, int n_in,
                              void* d_out, int out_size)
{
    const float* x     = (const float*)d_in[0];
    const float* battr = (const float*)d_in[1];
    const int*   upidx = (const int*)d_in[2];
    const int*   bidx  = (const int*)d_in[3];
    const float* eps1  = (const float*)d_in[4];
    const float* eps2  = (const float*)d_in[5];
    const float* uw1 = (const float*)d_in[6];
    const float* ub1 = (const float*)d_in[7];
    const float* ug1 = (const float*)d_in[8];
    const float* ube1= (const float*)d_in[9];
    const float* uw2 = (const float*)d_in[10];
    const float* ub2 = (const float*)d_in[11];
    const float* ug2 = (const float*)d_in[12];
    const float* ube2= (const float*)d_in[13];
    const float* bw1 = (const float*)d_in[14];
    const float* bb1 = (const float*)d_in[15];
    const float* bg1 = (const float*)d_in[16];
    const float* bbe1= (const float*)d_in[17];
    const float* bw2 = (const float*)d_in[18];
    const float* bb2 = (const float*)d_in[19];
    const float* bg2 = (const float*)d_in[20];
    const float* bbe2= (const float*)d_in[21];
    const float* cw  = (const float*)d_in[22];
    const float* cb  = (const float*)d_in[23];
    const float* cg  = (const float*)d_in[24];
    const float* cbe = (const float*)d_in[25];
    float* out = (float*)d_out;

    int N  = in_sizes[0] / HDIM;
    int EU = in_sizes[2] / 2;
    int EB = in_sizes[3] / 2;

    float *aggu, *aggb, *y1u, *y1b, *y2, *stats;
    cudaGetSymbolAddress((void**)&aggu,  g_aggu);
    cudaGetSymbolAddress((void**)&aggb,  g_aggb);
    cudaGetSymbolAddress((void**)&y1u,   g_y1u);
    cudaGetSymbolAddress((void**)&y1b,   g_y1b);
    cudaGetSymbolAddress((void**)&y2,    g_y2);
    cudaGetSymbolAddress((void**)&stats, g_stats);

    float invN = 1.0f / (float)N;
    int total4 = (N * HDIM) / 4;
    int gb = (N + 255) / 256;

    // edge index rows:
    // up:       dst = upidx[0..EU),   src = upidx[EU..2EU)
    // boundary: dst = bidx[EB..2EB),  src = bidx[0..EB)

    // Phase 0: init aggregates + zero stats
    init_kernel<<<592, 256>>>(x, eps1, eps2, aggu, aggb, stats, total4);

    // Phase 1: merged scatter-adds (vectorized RED)
    scatter2_kernel<<<10240, 256>>>(x, upidx, upidx + EU, EU,
                                    battr, bidx + EB, bidx, EB,
                                    aggu, aggb);

    // Phase 2: layer-1 GEMMs (merged dual launch, fused stats)
    {
        GArg gu = { aggu, uw1, ub1, nullptr, nullptr, nullptr,
                    nullptr, nullptr, nullptr, y1u, stats + 0 };
        GArg gv = { aggb, bw1, bb1, nullptr, nullptr, nullptr,
                    nullptr, nullptr, nullptr, y1b, stats + 128 };
        gemm_bn<64, false><<<dim3(gb, 2), 256>>>(gu, gv, 64, N, invN);
    }

    // Phase 3: layer-2 GEMMs, input BN+ReLU coeffs computed in-kernel
    {
        GArg gu = { y1u, uw2, ub2, stats + 0,   ug1, ube1,
                    stats + 0,   ug1, ube1, y2,      stats + 256 };
        GArg gv = { y1b, bw2, bb2, stats + 128, bg1, bbe1,
                    stats + 128, bg1, bbe1, y2 + 64, stats + 384 };
        gemm_bn<64, true><<<dim3(gb, 2), 256>>>(gu, gv, 128, N, invN);
    }

    // Phase 4: combine GEMM (K=128), input BN+ReLU from two stats sets
    {
        GArg gc = { y2, cw, cb, stats + 256, ug2, ube2,
                    stats + 384, bg2, bbe2, out, stats + 512 };
        gemm_bn<128, true><<<dim3(gb, 1), 256>>>(gc, gc, 64, N, invN);
    }

    // Phase 5: final BN+ReLU in place on out
    bnrelu_kernel<<<592, 256>>>(out, stats + 512, cg, cbe, total4, invN);
}